// round 15
// baseline (speedup 1.0000x reference)
#include <cuda_runtime.h>
#include <math.h>

#define CH 64
#define MAX_NODES 50000
#define NPB 64        // nodes per GEMM tile
#define ASTR 65       // A tile row stride (floats)

// Scratch accumulator: agg[dst] = sum scale * x[src]
__device__ float g_buf[MAX_NODES * CH];

// ---------------------------------------------------------------------------
// Kernel 1: edge scatter.  g_buf[dst] += ||edge_attr[e]|| * x[src]
// 16 threads/edge, one float4 per thread; leader loads metadata.
// Dtype probe inline: int64 (values < 2^31) => odd 32-bit words of the first
// 4 entries are zero; random int32 node ids make that ~(2e-5)^4 impossible.
// The probe words are L1-resident after the first warp.
// ---------------------------------------------------------------------------
__global__ void __launch_bounds__(256) edge_scatter_kernel(
    const float* __restrict__ x,
    const void* __restrict__ ei_raw,
    const float* __restrict__ ea,
    int E, int N)
{
    int t = blockIdx.x * blockDim.x + threadIdx.x;
    int e = t >> 4;
    if (e >= E) return;
    int lane = threadIdx.x & 15;
    int grpleader = threadIdx.x & 16;

    int src = 0, dst = 0;
    float scale = 0.f;
    if (lane == 0) {
        const int* e32 = (const int*)ei_raw;
        int hi = __ldg(&e32[1]) | __ldg(&e32[3]) | __ldg(&e32[5]) | __ldg(&e32[7]);
        if (hi == 0) {   // int64
            const long long* ei = (const long long*)ei_raw;
            src = (int)__ldg(&ei[e]);
            dst = (int)__ldg(&ei[E + e]);
        } else {         // int32
            src = __ldg(&e32[e]);
            dst = __ldg(&e32[E + e]);
        }
        float a0 = __ldg(&ea[3 * e + 0]);
        float a1 = __ldg(&ea[3 * e + 1]);
        float a2 = __ldg(&ea[3 * e + 2]);
        scale = sqrtf(a0 * a0 + a1 * a1 + a2 * a2);
    }
    src   = __shfl_sync(0xffffffffu, src,   grpleader);
    dst   = __shfl_sync(0xffffffffu, dst,   grpleader);
    scale = __shfl_sync(0xffffffffu, scale, grpleader);

    if ((unsigned)src >= (unsigned)N || (unsigned)dst >= (unsigned)N) return;

    float4 v = __ldg(reinterpret_cast<const float4*>(x + (size_t)src * CH) + lane);
    v.x *= scale; v.y *= scale; v.z *= scale; v.w *= scale;

    float* addr = g_buf + (size_t)dst * CH + lane * 4;
    asm volatile("red.global.add.v4.f32 [%0], {%1, %2, %3, %4};"
                 :: "l"(addr), "f"(v.x), "f"(v.y), "f"(v.z), "f"(v.w)
                 : "memory");
}

// ---------------------------------------------------------------------------
// GEMM pass: out_tile(64n x 64o) (+)= A_tile @ W^T, K=64.
// 256 threads, 33KB static smem (~6 blocks/SM), grid 782 = single wave.
// Per thread: 1 node x 16 outputs. Per k: 1 conflict-free scalar LDS (A)
// + 4 warp-uniform LDS.128 (W, broadcast) + 16 FFMA.
// ---------------------------------------------------------------------------
template <bool ACCUM>
__device__ __forceinline__ void gemm_pass(
    const float* __restrict__ A,
    const float* __restrict__ W,
    float* __restrict__ out,
    int N)
{
    __shared__ float As[CH * ASTR];   // As[k * 65 + n]  (16640 B)
    __shared__ float Ws[CH * CH];     // Ws[k * 64 + o]  (16384 B)
    int tid = threadIdx.x;
    int node0 = blockIdx.x * NPB;

    // Stage W transposed: o fast across lanes -> conflict-free STS.
    for (int idx = tid; idx < CH * CH; idx += 256) {
        int o = idx & 63;
        int k = idx >> 6;
        Ws[k * CH + o] = __ldg(&W[o * CH + k]);
    }

    // Stage A transposed: n fast across lanes -> conflict-free STS.
    for (int idx4 = tid; idx4 < NPB * 16; idx4 += 256) {
        int n  = idx4 & 63;
        int i4 = idx4 >> 6;
        int gn = node0 + n;
        float4 v = make_float4(0.f, 0.f, 0.f, 0.f);
        if (gn < N) {
            v = __ldg(reinterpret_cast<const float4*>(A + (size_t)gn * CH) + i4);
        }
        int k = i4 * 4;
        As[(k + 0) * ASTR + n] = v.x;
        As[(k + 1) * ASTR + n] = v.y;
        As[(k + 2) * ASTR + n] = v.z;
        As[(k + 3) * ASTR + n] = v.w;
    }
    __syncthreads();

    int nl = tid & 63;            // this thread's node within the tile
    int ow = (tid >> 6) * 4;      // float4 offset of this thread's 16 outputs
    const float4* Wv = reinterpret_cast<const float4*>(Ws);

    float acc[16];
    #pragma unroll
    for (int o = 0; o < 16; o++) acc[o] = 0.f;

    #pragma unroll 4
    for (int k = 0; k < CH; k++) {
        float a = As[k * ASTR + nl];          // bank (k+nl)%32: conflict-free
        const float4* wr = Wv + k * 16 + ow;  // warp-uniform -> broadcast
        float4 w0 = wr[0], w1 = wr[1], w2 = wr[2], w3 = wr[3];
        acc[0]  += a * w0.x; acc[1]  += a * w0.y; acc[2]  += a * w0.z; acc[3]  += a * w0.w;
        acc[4]  += a * w1.x; acc[5]  += a * w1.y; acc[6]  += a * w1.z; acc[7]  += a * w1.w;
        acc[8]  += a * w2.x; acc[9]  += a * w2.y; acc[10] += a * w2.z; acc[11] += a * w2.w;
        acc[12] += a * w3.x; acc[13] += a * w3.y; acc[14] += a * w3.z; acc[15] += a * w3.w;
    }

    int gn = node0 + nl;
    if (gn < N) {
        float4* d4 = reinterpret_cast<float4*>(out + (size_t)gn * CH) + ow;
        #pragma unroll
        for (int q = 0; q < 4; q++) {
            float4 r = make_float4(acc[4 * q + 0], acc[4 * q + 1],
                                   acc[4 * q + 2], acc[4 * q + 3]);
            if (ACCUM) {
                float4 p = d4[q];
                r.x += p.x; r.y += p.y; r.z += p.z; r.w += p.w;
            }
            d4[q] = r;
        }
    }
}

// out = x @ psi^T  (independent of scatter; runs on side stream)
__global__ void __launch_bounds__(256) psi_gemm_kernel(
    const float* __restrict__ x,
    const float* __restrict__ psi,
    float* __restrict__ out,
    int N)
{
    gemm_pass<false>(x, psi, out, N);
}

// out += g_buf @ phi^T  (after scatter + psi pass)
__global__ void __launch_bounds__(256) phi_gemm_kernel(
    const float* __restrict__ phi,
    float* __restrict__ out,
    int N)
{
    gemm_pass<true>(g_buf, phi, out, N);
}

// ---------------------------------------------------------------------------
// Launch: fork-join graph.
//   s0: memset(g_buf) -> scatter -> (join) -> phi_gemm
//   s1:               -> psi_gemm ----^
// If the side stream is unavailable, everything runs on s0 (events on the
// same stream are no-ops) -> sequential but correct.
// ---------------------------------------------------------------------------
extern "C" void kernel_launch(void* const* d_in, const int* in_sizes, int n_in,
                              void* d_out, int out_size) {
    const float* x   = (const float*)d_in[0];
    const void*  ei  = d_in[1];
    const float* ea  = (const float*)d_in[2];
    const float* phi = (const float*)d_in[3];
    const float* psi = (const float*)d_in[4];
    float*       out = (float*)d_out;

    int N = in_sizes[0] / CH;   // 50000
    int E = in_sizes[1] / 2;    // 800000

    static cudaStream_t s1 = 0;
    static cudaEvent_t evA = 0, evB = 0;
    static int inited = 0;
    if (!inited) {
        cudaStream_t tmp;
        if (cudaStreamCreateWithFlags(&tmp, cudaStreamNonBlocking) == cudaSuccess)
            s1 = tmp;
        cudaEventCreateWithFlags(&evA, cudaEventDisableTiming);
        cudaEventCreateWithFlags(&evB, cudaEventDisableTiming);
        inited = 1;
    }

    float* buf = nullptr;
    cudaGetSymbolAddress((void**)&buf, g_buf);

    // Fork: psi GEMM on s1 runs concurrently with memset+scatter on s0.
    cudaEventRecord(evA, 0);
    cudaStreamWaitEvent(s1, evA, 0);

    cudaMemsetAsync(buf, 0, (size_t)N * CH * sizeof(float), 0);

    int ngrid = (N + NPB - 1) / NPB;   // 782
    psi_gemm_kernel<<<ngrid, 256, 0, s1>>>(x, psi, out, N);

    long long tot = (long long)E * 16;
    int eblocks = (int)((tot + 255) / 256);
    edge_scatter_kernel<<<eblocks, 256>>>(x, ei, ea, E, N);

    // Join: phi GEMM needs both the scatter result and psi's out.
    cudaEventRecord(evB, s1);
    cudaStreamWaitEvent(0, evB, 0);

    phi_gemm_kernel<<<ngrid, 256>>>(phi, out, N);
}

// round 16
// speedup vs baseline: 1.1789x; 1.1789x over previous
#include <cuda_runtime.h>
#include <math.h>

#define CH 64
#define MAX_NODES 50000
#define NPB 128       // nodes per GEMM tile
#define ASTR 128      // A tile [k][n] row stride (bank = n: conflict-free)
#define WSTR 64       // W tile [k][o] row stride (uniform reads: no conflicts)

// Scratch accumulator: g_buf[dst] = sum scale * x[src]
__device__ float g_buf[MAX_NODES * CH];

// ---------------------------------------------------------------------------
// Kernel 1: edge scatter.  g_buf[dst] += ||edge_attr[e]|| * x[src]
// 16 threads/edge, one float4 per thread; leader loads metadata.
// Dtype probe per block into smem (before any divergent exit): int64 with
// values < 2^31 => odd 32-bit words of first 4 entries are all zero —
// impossible for random int32 node ids (~(2e-5)^4). The 4 probe words are
// L1/L2-hot; cost hides under other warps.
// ---------------------------------------------------------------------------
__global__ void __launch_bounds__(256) edge_scatter_kernel(
    const float* __restrict__ x,
    const void* __restrict__ ei_raw,
    const float* __restrict__ ea,
    int E, int N)
{
    __shared__ int s_is64;
    if (threadIdx.x == 0) {
        const int* e32 = (const int*)ei_raw;
        int hi = __ldg(&e32[1]) | __ldg(&e32[3]) | __ldg(&e32[5]) | __ldg(&e32[7]);
        s_is64 = (hi == 0) ? 1 : 0;
    }
    __syncthreads();

    int t = blockIdx.x * blockDim.x + threadIdx.x;
    int e = t >> 4;
    if (e >= E) return;
    int lane = threadIdx.x & 15;
    int grpleader = threadIdx.x & 16;

    int src = 0, dst = 0;
    float scale = 0.f;
    if (lane == 0) {
        if (s_is64) {
            const long long* ei = (const long long*)ei_raw;
            src = (int)__ldg(&ei[e]);
            dst = (int)__ldg(&ei[E + e]);
        } else {
            const int* ei = (const int*)ei_raw;
            src = __ldg(&ei[e]);
            dst = __ldg(&ei[E + e]);
        }
        float a0 = __ldg(&ea[3 * e + 0]);
        float a1 = __ldg(&ea[3 * e + 1]);
        float a2 = __ldg(&ea[3 * e + 2]);
        scale = sqrtf(a0 * a0 + a1 * a1 + a2 * a2);
    }
    src   = __shfl_sync(0xffffffffu, src,   grpleader);
    dst   = __shfl_sync(0xffffffffu, dst,   grpleader);
    scale = __shfl_sync(0xffffffffu, scale, grpleader);

    if ((unsigned)src >= (unsigned)N || (unsigned)dst >= (unsigned)N) return;

    float4 v = __ldg(reinterpret_cast<const float4*>(x + (size_t)src * CH) + lane);
    v.x *= scale; v.y *= scale; v.z *= scale; v.w *= scale;

    float* addr = g_buf + (size_t)dst * CH + lane * 4;
    asm volatile("red.global.add.v4.f32 [%0], {%1, %2, %3, %4};"
                 :: "l"(addr), "f"(v.x), "f"(v.y), "f"(v.z), "f"(v.w)
                 : "memory");
}

// ---------------------------------------------------------------------------
// GEMM pass: out_tile(128n x 64o) (+)= A_tile @ W^T, K=64.
// 256 threads, 48KB static smem -> 4 blocks/SM, grid 391 -> single wave.
// Per thread: 4 strided nodes (tn+32j) x 8 outputs = 32 accumulators.
// Per k: 4 scalar LDS (bank = lane) + 2 aligned warp-uniform LDS.128
// (broadcast) + 32 FFMA.
// ---------------------------------------------------------------------------
template <bool ACCUM>
__device__ __forceinline__ void gemm_pass(
    const float* __restrict__ A,
    const float* __restrict__ W,
    float* __restrict__ out,
    int N)
{
    __shared__ float As[CH * ASTR];   // As[k * 128 + n]  (32768 B)
    __shared__ float Ws[CH * WSTR];   // Ws[k * 64 + o]   (16384 B)
    int tid = threadIdx.x;
    int node0 = blockIdx.x * NPB;

    // Stage W: Ws[k][o] = W[o][k]; o fast across lanes -> bank = o%32,
    // conflict-free STS.
    for (int idx = tid; idx < CH * CH; idx += 256) {
        int o = idx & 63;
        int k = idx >> 6;
        Ws[k * WSTR + o] = __ldg(&W[o * CH + k]);
    }

    // Stage A transposed into [k][n]: n varies across lanes -> STS bank = n%32
    // (conflict-free; all other offsets are multiples of 32).
    for (int idx4 = tid; idx4 < NPB * 16; idx4 += 256) {
        int n = idx4 & 127;
        int c = idx4 >> 7;
        int gn = node0 + n;
        float4 v = make_float4(0.f, 0.f, 0.f, 0.f);
        if (gn < N) {
            v = __ldg(reinterpret_cast<const float4*>(A + (size_t)gn * CH) + c);
        }
        int k = 4 * c;
        As[(k + 0) * ASTR + n] = v.x;
        As[(k + 1) * ASTR + n] = v.y;
        As[(k + 2) * ASTR + n] = v.z;
        As[(k + 3) * ASTR + n] = v.w;
    }
    __syncthreads();

    int tn = tid & 31;          // lane: handles nodes tn, tn+32, tn+64, tn+96
    int ob = (tid >> 5) * 8;    // 8 consecutive outputs (warp-uniform)

    float acc[4][8];
    #pragma unroll
    for (int j = 0; j < 4; j++)
        #pragma unroll
        for (int o = 0; o < 8; o++) acc[j][o] = 0.f;

    #pragma unroll 4
    for (int k = 0; k < CH; k++) {
        const float* ar = As + k * ASTR + tn;
        float a0 = ar[0];       // bank = tn: conflict-free
        float a1 = ar[32];
        float a2 = ar[64];
        float a3 = ar[96];
        const float4* wr = reinterpret_cast<const float4*>(Ws + k * WSTR + ob);
        float4 w0 = wr[0];      // warp-uniform, 16B-aligned -> broadcast
        float4 w1 = wr[1];
        float w[8] = {w0.x, w0.y, w0.z, w0.w, w1.x, w1.y, w1.z, w1.w};
        #pragma unroll
        for (int o = 0; o < 8; o++) acc[0][o] += a0 * w[o];
        #pragma unroll
        for (int o = 0; o < 8; o++) acc[1][o] += a1 * w[o];
        #pragma unroll
        for (int o = 0; o < 8; o++) acc[2][o] += a2 * w[o];
        #pragma unroll
        for (int o = 0; o < 8; o++) acc[3][o] += a3 * w[o];
    }

    #pragma unroll
    for (int j = 0; j < 4; j++) {
        int gn = node0 + tn + 32 * j;
        if (gn < N) {
            float4* orow = reinterpret_cast<float4*>(out + (size_t)gn * CH + ob);
            float4 r0 = make_float4(acc[j][0], acc[j][1], acc[j][2], acc[j][3]);
            float4 r1 = make_float4(acc[j][4], acc[j][5], acc[j][6], acc[j][7]);
            if (ACCUM) {
                float4 p0 = orow[0], p1 = orow[1];
                r0.x += p0.x; r0.y += p0.y; r0.z += p0.z; r0.w += p0.w;
                r1.x += p1.x; r1.y += p1.y; r1.z += p1.z; r1.w += p1.w;
            }
            orow[0] = r0;
            orow[1] = r1;
        }
    }
}

// out = x @ psi^T
__global__ void __launch_bounds__(256) psi_gemm_kernel(
    const float* __restrict__ x,
    const float* __restrict__ psi,
    float* __restrict__ out,
    int N)
{
    gemm_pass<false>(x, psi, out, N);
}

// out += g_buf @ phi^T
__global__ void __launch_bounds__(256) phi_gemm_kernel(
    const float* __restrict__ phi,
    float* __restrict__ out,
    int N)
{
    gemm_pass<true>(g_buf, phi, out, N);
}

// ---------------------------------------------------------------------------
// Launch (single stream): memset(g_buf) -> scatter -> psi -> phi.
// ---------------------------------------------------------------------------
extern "C" void kernel_launch(void* const* d_in, const int* in_sizes, int n_in,
                              void* d_out, int out_size) {
    const float* x   = (const float*)d_in[0];
    const void*  ei  = d_in[1];
    const float* ea  = (const float*)d_in[2];
    const float* phi = (const float*)d_in[3];
    const float* psi = (const float*)d_in[4];
    float*       out = (float*)d_out;

    int N = in_sizes[0] / CH;   // 50000
    int E = in_sizes[1] / 2;    // 800000

    float* buf = nullptr;
    cudaGetSymbolAddress((void**)&buf, g_buf);
    cudaMemsetAsync(buf, 0, (size_t)N * CH * sizeof(float));

    long long tot = (long long)E * 16;
    int eblocks = (int)((tot + 255) / 256);
    edge_scatter_kernel<<<eblocks, 256>>>(x, ei, ea, E, N);

    int ngrid = (N + NPB - 1) / NPB;   // 391 -> single wave at 4 blocks/SM
    psi_gemm_kernel<<<ngrid, 256>>>(x, psi, out, N);
    phi_gemm_kernel<<<ngrid, 256>>>(phi, out, N);
}

// round 17
// speedup vs baseline: 1.4238x; 1.2077x over previous
#include <cuda_runtime.h>
#include <math.h>

#define CH 64
#define MAX_NODES 50000
#define KS 128        // concat K dim: [x | g_buf]
#define NPB 128       // nodes per GEMM tile
#define ASTR 129      // A tile stride (odd -> conflict-free strided reads)
#define WSTR 65       // W tile stride
#define GEMM_SMEM ((KS * ASTR + KS * WSTR) * (int)sizeof(float))  // 99328 B

// Scratch accumulator: g_buf[dst] = sum scale * x[src]
__device__ float g_buf[MAX_NODES * CH];

// ---------------------------------------------------------------------------
// Kernel 1: edge scatter.  g_buf[dst] += ||edge_attr[e]|| * x[src]
// 16 threads/edge, one float4 per thread. NO leader/shuffles: every lane
// loads the (shared) edge metadata directly — same address within the
// 16-lane group -> single broadcast L1 transaction, no 26-cycle SHFL chain.
// Dtype probe per block into smem: int64 with values < 2^31 => odd 32-bit
// words of the first 4 entries all zero (impossible for random int32 ids).
// ---------------------------------------------------------------------------
__global__ void __launch_bounds__(256) edge_scatter_kernel(
    const float* __restrict__ x,
    const void* __restrict__ ei_raw,
    const float* __restrict__ ea,
    int E, int N)
{
    __shared__ int s_is64;
    if (threadIdx.x == 0) {
        const int* e32 = (const int*)ei_raw;
        int hi = __ldg(&e32[1]) | __ldg(&e32[3]) | __ldg(&e32[5]) | __ldg(&e32[7]);
        s_is64 = (hi == 0) ? 1 : 0;
    }
    __syncthreads();

    int t = blockIdx.x * blockDim.x + threadIdx.x;
    int e = t >> 4;
    if (e >= E) return;
    int lane = threadIdx.x & 15;

    int src, dst;
    if (s_is64) {
        const long long* ei = (const long long*)ei_raw;
        src = (int)__ldg(&ei[e]);
        dst = (int)__ldg(&ei[E + e]);
    } else {
        const int* ei = (const int*)ei_raw;
        src = __ldg(&ei[e]);
        dst = __ldg(&ei[E + e]);
    }
    float a0 = __ldg(&ea[3 * e + 0]);
    float a1 = __ldg(&ea[3 * e + 1]);
    float a2 = __ldg(&ea[3 * e + 2]);
    float scale = sqrtf(a0 * a0 + a1 * a1 + a2 * a2);

    if ((unsigned)src >= (unsigned)N || (unsigned)dst >= (unsigned)N) return;

    float4 v = __ldg(reinterpret_cast<const float4*>(x + (size_t)src * CH) + lane);
    v.x *= scale; v.y *= scale; v.z *= scale; v.w *= scale;

    float* addr = g_buf + (size_t)dst * CH + lane * 4;
    asm volatile("red.global.add.v4.f32 [%0], {%1, %2, %3, %4};"
                 :: "l"(addr), "f"(v.x), "f"(v.y), "f"(v.z), "f"(v.w)
                 : "memory");
}

// ---------------------------------------------------------------------------
// Kernel 2: fused GEMM   out = [x | g_buf] @ [psi ; phi]^T   (R3-proven)
// Tile: 128 nodes x 64 outputs x K=128. 256 threads.
// Per thread: 4 strided nodes (tn+32j) x 8 outputs -> 32 accumulators.
// ---------------------------------------------------------------------------
extern __shared__ float smem[];

__global__ void __launch_bounds__(256) fused_gemm_kernel(
    const float* __restrict__ x,
    const float* __restrict__ phi,
    const float* __restrict__ psi,
    float* __restrict__ out,
    int N)
{
    float* As = smem;                 // As[k * ASTR + n]
    float* Ws = smem + KS * ASTR;     // Ws[k * WSTR + o]
    int tid = threadIdx.x;
    int node0 = blockIdx.x * NPB;

    // Stage W: [psi ; phi] -> Ws[i][o]; coalesced LDG.
    for (int idx = tid; idx < CH * KS; idx += 256) {
        int o = idx >> 7;
        int i = idx & 127;
        float v = (i < CH) ? __ldg(&psi[o * CH + i])
                           : __ldg(&phi[o * CH + (i - CH)]);
        Ws[i * WSTR + o] = v;
    }

    // Stage A: float4 LDG from x / g_buf, scalar STS transpose into [k][n].
    for (int idx4 = tid; idx4 < NPB * 32; idx4 += 256) {
        int n  = idx4 >> 5;        // node within tile
        int i4 = idx4 & 31;        // which float4 of the 128-float concat row
        int gn = node0 + n;
        float4 v = make_float4(0.f, 0.f, 0.f, 0.f);
        if (gn < N) {
            v = (i4 < 16)
                ? __ldg(reinterpret_cast<const float4*>(x + (size_t)gn * CH) + i4)
                : __ldg(reinterpret_cast<const float4*>(g_buf + (size_t)gn * CH) + (i4 - 16));
        }
        int i = i4 * 4;
        As[(i + 0) * ASTR + n] = v.x;
        As[(i + 1) * ASTR + n] = v.y;
        As[(i + 2) * ASTR + n] = v.z;
        As[(i + 3) * ASTR + n] = v.w;
    }
    __syncthreads();

    int tn = tid & 31;     // node lane (strided nodes tn + 32j)
    int to = tid >> 5;     // output group
    int ob = to * 8;

    float acc[4][8];
    #pragma unroll
    for (int j = 0; j < 4; j++)
        #pragma unroll
        for (int o = 0; o < 8; o++) acc[j][o] = 0.f;

    #pragma unroll 4
    for (int k = 0; k < KS; k++) {
        const float* ar = As + k * ASTR + tn;
        const float* wr = Ws + k * WSTR + ob;
        float a[4], w[8];
        #pragma unroll
        for (int j = 0; j < 4; j++) a[j] = ar[32 * j];
        #pragma unroll
        for (int o = 0; o < 8; o++) w[o] = wr[o];
        #pragma unroll
        for (int j = 0; j < 4; j++)
            #pragma unroll
            for (int o = 0; o < 8; o++)
                acc[j][o] += a[j] * w[o];
    }

    #pragma unroll
    for (int j = 0; j < 4; j++) {
        int gn = node0 + tn + 32 * j;
        if (gn < N) {
            float4* orow = reinterpret_cast<float4*>(out + (size_t)gn * CH + ob);
            orow[0] = make_float4(acc[j][0], acc[j][1], acc[j][2], acc[j][3]);
            orow[1] = make_float4(acc[j][4], acc[j][5], acc[j][6], acc[j][7]);
        }
    }
}

// ---------------------------------------------------------------------------
// Launch: memset(g_buf) -> scatter -> fused GEMM.
// ---------------------------------------------------------------------------
extern "C" void kernel_launch(void* const* d_in, const int* in_sizes, int n_in,
                              void* d_out, int out_size) {
    const float* x   = (const float*)d_in[0];
    const void*  ei  = d_in[1];
    const float* ea  = (const float*)d_in[2];
    const float* phi = (const float*)d_in[3];
    const float* psi = (const float*)d_in[4];
    float*       out = (float*)d_out;

    int N = in_sizes[0] / CH;   // 50000
    int E = in_sizes[1] / 2;    // 800000

    float* buf = nullptr;
    cudaGetSymbolAddress((void**)&buf, g_buf);
    cudaMemsetAsync(buf, 0, (size_t)N * CH * sizeof(float));

    long long tot = (long long)E * 16;
    int eblocks = (int)((tot + 255) / 256);
    edge_scatter_kernel<<<eblocks, 256>>>(x, ei, ea, E, N);

    cudaFuncSetAttribute(fused_gemm_kernel,
                         cudaFuncAttributeMaxDynamicSharedMemorySize,
                         GEMM_SMEM);
    fused_gemm_kernel<<<(N + NPB - 1) / NPB, 256, GEMM_SMEM>>>(x, phi, psi, out, N);
}